// round 17
// baseline (speedup 1.0000x reference)
#include <cuda_runtime.h>

#define THREADS 512
#define TT 30
#define RS 68   // state row stride (swizzle padding)

typedef unsigned long long ull;

// ------- dup-weight global scratch: [k][u][g][2] per layer -------
#define D1  0        // L1  [80][64][4][2]  = 40960
#define D2  40960    // L2  [96][32][4][2]  = 24576
#define D3  65536    // W3hh[32][32][4][2]  = 8192
#define DI3 73728    // Wih3[32][32][4][2]  = 8192
#define D4  81920    // L4  [96][64][4][2]  = 49152
__device__ __align__(128) float g_wd[131072];

// ------- shared memory layout (float offsets) -------
#define B1o   0      // 256 (interleaved [u][g])
#define B2o   256    // 128
#define B3o   384    // 128
#define B4o   512    // 256
#define BOo   768    // 16
#define WOd   784    // Wout dup pairs [64][32] = 2048
// state [k][row] stride RS, rows swizzled: phys(r) = r + 4*(r>=32)
#define XINo  2832   // 2 x [16][68] = 2176
#define H1o   5008   // 2 x [64][68] = 8704   (P2: h4)
#define H2o   13712  // 2 x [32][68] = 4352   (P2: h3)
#define SHF   18064  // 72256 bytes

__device__ __forceinline__ void ffma2(ull &acc, ull a, ull b){
    asm("fma.rn.f32x2 %0, %1, %2, %0;" : "+l"(acc) : "l"(a), "l"(b));
}
__device__ __forceinline__ ull bcast2(float w){
    ull r; asm("mov.b64 %0, {%1, %1};" : "=l"(r) : "f"(w)); return r;
}
__device__ __forceinline__ float2 unpack2(ull v){
    float2 f; asm("mov.b64 {%0, %1}, %2;" : "=f"(f.x), "=f"(f.y) : "l"(v)); return f;
}
__device__ __forceinline__ float ex2x(float x){
    float e; asm("ex2.approx.f32 %0, %1;" : "=f"(e) : "f"(x)); return e;
}
__device__ __forceinline__ float rcpx(float x){
    float r; asm("rcp.approx.f32 %0, %1;" : "=f"(r) : "f"(x)); return r;
}

// 8-MUFU LSTM activation (gate order i,f,g,o). Returns h, updates c.
__device__ __forceinline__ float act8(float zi, float zf, float zg, float zo, float &c){
    const float K1 = -1.4426950408889634f;
    float ei = ex2x(K1 * zi);
    float ef = ex2x(K1 * zf);
    float eg = ex2x(2.0f * K1 * zg);
    float eo = ex2x(K1 * zo);
    float A = 1.0f + ei, F = 1.0f + ef, G = 1.0f + eg, O = 1.0f + eo;
    float it = (1.0f - eg) * rcpx(A * G);
    float cn = fmaf(c, rcpx(F), it);
    float ec = ex2x(2.0f * K1 * cn);
    float C = 1.0f + ec;
    c = cn;
    return (1.0f - ec) * rcpx(O * C);
}

// acc[j][g][p] += sum_k W[k][u0+j][g] * in[k][rows]
// in: SHARED [k][row] stride RS (1 LDS.128 per k)
// Wd: GLOBAL dup pairs, pre-offset by u0*8; WK = floats per k (= U_layer*8)
template<int NU>
__device__ __forceinline__ void accumG(const float* __restrict__ in,
                                       const float* __restrict__ Wd, int WK,
                                       int K, ull (&acc)[NU][4][2], int pr0)
{
#pragma unroll 4
    for (int k = 0; k < K; k++) {
        ulonglong2 h = *reinterpret_cast<const ulonglong2*>(in + k*RS + pr0);
#pragma unroll
        for (int j = 0; j < NU; j++) {
            ulonglong2 wA = *reinterpret_cast<const ulonglong2*>(Wd + k*WK + j*8);
            ulonglong2 wB = *reinterpret_cast<const ulonglong2*>(Wd + k*WK + j*8 + 4);
            ffma2(acc[j][0][0], wA.x, h.x); ffma2(acc[j][0][1], wA.x, h.y);
            ffma2(acc[j][1][0], wA.y, h.x); ffma2(acc[j][1][1], wA.y, h.y);
            ffma2(acc[j][2][0], wB.x, h.x); ffma2(acc[j][2][1], wB.x, h.y);
            ffma2(acc[j][3][0], wB.y, h.x); ffma2(acc[j][3][1], wB.y, h.y);
        }
    }
}

template<int NU>
__device__ __forceinline__ void init_acc(ull (&acc)[NU][4][2], const ull (&b)[NU][4]){
#pragma unroll
    for (int j = 0; j < NU; j++)
#pragma unroll
        for (int g = 0; g < 4; g++) {
            acc[j][g][0] = b[j][g];
            acc[j][g][1] = b[j][g];
        }
}

// activation + STS.128 h store; hdst pre-offset by u0*RS.
template<int NU>
__device__ __forceinline__ void act_store(ull (&acc)[NU][4][2], float (&c)[NU][4],
                                          float* hdst, int pr0)
{
#pragma unroll
    for (int j = 0; j < NU; j++) {
        float2 zi0 = unpack2(acc[j][0][0]), zi1 = unpack2(acc[j][0][1]);
        float2 zf0 = unpack2(acc[j][1][0]), zf1 = unpack2(acc[j][1][1]);
        float2 zg0 = unpack2(acc[j][2][0]), zg1 = unpack2(acc[j][2][1]);
        float2 zo0 = unpack2(acc[j][3][0]), zo1 = unpack2(acc[j][3][1]);
        float4 hv;
        hv.x = act8(zi0.x, zf0.x, zg0.x, zo0.x, c[j][0]);
        hv.y = act8(zi0.y, zf0.y, zg0.y, zo0.y, c[j][1]);
        hv.z = act8(zi1.x, zf1.x, zg1.x, zo1.x, c[j][2]);
        hv.w = act8(zi1.y, zf1.y, zg1.y, zo1.y, c[j][3]);
        *reinterpret_cast<float4*>(hdst + j*RS + pr0) = hv;
    }
}

// -------- prep kernel: build dup-pair weight buffer --------
__global__ void prep_w(const float* __restrict__ Wih1, const float* __restrict__ Whh1,
                       const float* __restrict__ Wih2, const float* __restrict__ Whh2,
                       const float* __restrict__ Wih3, const float* __restrict__ Whh3,
                       const float* __restrict__ Wih4, const float* __restrict__ Whh4)
{
    int i = blockIdx.x * blockDim.x + threadIdx.x;
    if (i >= 131072) return;
    float v;
    if (i < D2) {                      // L1: [80][64][4][2]
        int q = i >> 1, g = q & 3, u = (q >> 2) & 63, k = q >> 8;
        v = (k < 16) ? Wih1[(g * 64 + u) * 16 + k] : Whh1[(g * 64 + u) * 64 + (k - 16)];
    } else if (i < D3) {               // L2: [96][32][4][2]
        int q = (i - D2) >> 1, g = q & 3, u = (q >> 2) & 31, k = q >> 7;
        v = (k < 64) ? Wih2[(g * 32 + u) * 64 + k] : Whh2[(g * 32 + u) * 32 + (k - 64)];
    } else if (i < DI3) {              // W3hh: [32][32][4][2]
        int q = (i - D3) >> 1, g = q & 3, u = (q >> 2) & 31, k = q >> 7;
        v = Whh3[(g * 32 + u) * 32 + k];
    } else if (i < D4) {               // Wih3: [32][32][4][2]
        int q = (i - DI3) >> 1, g = q & 3, u = (q >> 2) & 31, k = q >> 7;
        v = Wih3[(g * 32 + u) * 32 + k];
    } else {                           // L4: [96][64][4][2]
        int q = (i - D4) >> 1, g = q & 3, u = (q >> 2) & 63, k = q >> 8;
        v = (k < 32) ? Wih4[(g * 64 + u) * 32 + k] : Whh4[(g * 64 + u) * 64 + (k - 32)];
    }
    g_wd[i] = v;
}

__global__ void __launch_bounds__(THREADS, 1)
lstm_ae(const float* __restrict__ x,
        const float* __restrict__ b1, const float* __restrict__ b2,
        const float* __restrict__ b3, const float* __restrict__ b4,
        const float* __restrict__ Wout, const float* __restrict__ bout,
        float* __restrict__ out)
{
    extern __shared__ float sh[];
    const int tid = threadIdx.x;
    const int wid = tid >> 5;
    const bool grpA = ((wid >> 2) & 1) == 0;   // 2 A + 2 B warps per SMSP
    const long row0 = (long)blockIdx.x * 64;

    // gemm tiling: rows common to all layers, 4 per thread
    const int r0  = (tid & 15) * 4;
    const int pr0 = r0 + ((r0 & 32) >> 3);
    const int uA0 = (tid >> 4) * 2;     // H=64 layers: 2 units
    const int uB  = tid >> 4;           // H=32 layers: 1 unit
    // x io: 1 row x 2 features
    const int xr  = tid >> 3;
    const int xf0 = (tid & 7) * 2;
    const int prx = xr + ((xr & 32) >> 3);
    // projection: 1 feature x 2 rows
    const int fo = tid & 15, rb = tid >> 4;
    const int rr = rb * 2;
    const int prb = rr + ((rr & 32) >> 3);

    const float* gW1  = g_wd + D1  + uA0 * 8;   // WK=512
    const float* gW2  = g_wd + D2  + uB * 8;    // WK=256
    const float* gW3  = g_wd + D3  + uB * 8;    // WK=256
    const float* gWI3 = g_wd + DI3 + uB * 8;    // WK=256
    const float* gW4  = g_wd + D4  + uA0 * 8;   // WK=512

    // ---- biases + dup-Wout staging, zero state ----
    if (tid < 256) { int u = tid >> 2, g = tid & 3; sh[B1o + tid] = b1[g * 64 + u]; }
    if (tid < 128) { int u = tid >> 2, g = tid & 3; sh[B2o + tid] = b2[g * 32 + u]; }
    if (tid < 128) { int u = tid >> 2, g = tid & 3; sh[B3o + tid] = b3[g * 32 + u]; }
    if (tid < 256) { int u = tid >> 2, g = tid & 3; sh[B4o + tid] = b4[g * 64 + u]; }
    if (tid < 16)  sh[BOo + tid] = bout[tid];
    for (int i = tid; i < 2048; i += THREADS) {            // Wout dup pairs
        int j = i >> 5, f = (i & 31) >> 1;
        sh[WOd + i] = Wout[f * 64 + j];
    }
    for (int i = tid; i < 4352; i += THREADS) sh[H1o + i] = 0.f;   // h1 buf0
    for (int i = tid; i < 2176; i += THREADS) sh[H2o + i] = 0.f;   // h2 buf0
    {   // x(0) -> XIN buf0
        float2 gx = *reinterpret_cast<const float2*>(x + (row0 + xr) * (TT * 16) + xf0);
        sh[XINo + (xf0    ) * RS + prx] = gx.x;
        sh[XINo + (xf0 + 1) * RS + prx] = gx.y;
    }
    __syncthreads();

    ull b1p[2][4], b2p[1][4];
#pragma unroll
    for (int j = 0; j < 2; j++)
#pragma unroll
        for (int g = 0; g < 4; g++) b1p[j][g] = bcast2(sh[B1o + (uA0 + j) * 4 + g]);
#pragma unroll
    for (int g = 0; g < 4; g++) b2p[0][g] = bcast2(sh[B2o + uB * 4 + g]);

    float c1[2][4], c2[1][4];
#pragma unroll
    for (int j = 0; j < 2; j++)
#pragma unroll
        for (int q = 0; q < 4; q++) c1[j][q] = 0.f;
#pragma unroll
    for (int q = 0; q < 4; q++) c2[0][q] = 0.f;

    // ---- phase 1: encoder. accL1 enters each t as b1 + Whh1@h1(t-1). ----
    ull accL1[2][4][2], accL2[1][4][2];
    init_acc<2>(accL1, b1p);                 // h1(-1) = 0

    for (int t = 0; t < TT; t++) {
        const int p = t & 1;
        float2 gx;
        const bool pf = (t + 1 < TT);
        if (pf) gx = *reinterpret_cast<const float2*>(
            x + (row0 + xr) * (TT * 16) + (t + 1) * 16 + xf0);
        accumG<2>(sh + XINo + p * 1088, gW1, 512, 16, accL1, pr0);
        if (pf) {
            float* xb = sh + XINo + (p ^ 1) * 1088;
            xb[(xf0    ) * RS + prx] = gx.x;
            xb[(xf0 + 1) * RS + prx] = gx.y;
        }
        if (grpA) {
            act_store<2>(accL1, c1, sh + H1o + (p ^ 1) * 4352 + uA0 * RS, pr0);
            init_acc<1>(accL2, b2p);
            accumG<1>(sh + H2o + p * 2176, gW2 + 64 * 256, 256, 32, accL2, pr0);
        } else {
            init_acc<1>(accL2, b2p);
            accumG<1>(sh + H2o + p * 2176, gW2 + 64 * 256, 256, 32, accL2, pr0);
            act_store<2>(accL1, c1, sh + H1o + (p ^ 1) * 4352 + uA0 * RS, pr0);
        }
        __syncthreads();
        accumG<1>(sh + H1o + (p ^ 1) * 4352, gW2, 256, 64, accL2, pr0);
        if (grpA) {
            act_store<1>(accL2, c2, sh + H2o + (p ^ 1) * 2176 + uB * RS, pr0);
            init_acc<2>(accL1, b1p);
            accumG<2>(sh + H1o + (p ^ 1) * 4352, gW1 + 16 * 512, 512, 64, accL1, pr0);
        } else {
            init_acc<2>(accL1, b1p);
            accumG<2>(sh + H1o + (p ^ 1) * 4352, gW1 + 16 * 512, 512, 64, accL1, pr0);
            act_store<1>(accL2, c2, sh + H2o + (p ^ 1) * 2176 + uB * RS, pr0);
        }
        __syncthreads();
    }
    // latent = h2(29) in H2 buf 0

    // zin3 = Wih3 @ latent + b3 (constant over t), in registers
    ull zin3[1][4][2];
    {
        ull b3p[1][4];
#pragma unroll
        for (int g = 0; g < 4; g++) b3p[0][g] = bcast2(sh[B3o + uB * 4 + g]);
        init_acc<1>(zin3, b3p);
        accumG<1>(sh + H2o, gWI3, 256, 32, zin3, pr0);
        __syncthreads();   // latent reads done before H2 reuse as h3
        for (int i = tid; i < 2176; i += THREADS) sh[H2o + i] = 0.f;  // h3 buf0
        for (int i = tid; i < 4352; i += THREADS) sh[H1o + i] = 0.f;  // h4 buf0
    }
    __syncthreads();

    ull b4p[2][4];
#pragma unroll
    for (int j = 0; j < 2; j++)
#pragma unroll
        for (int g = 0; g < 4; g++) b4p[j][g] = bcast2(sh[B4o + (uA0 + j) * 4 + g]);
    const ull boutp = bcast2(sh[BOo + fo]);

    float c3[1][4], c4[2][4];
#pragma unroll
    for (int q = 0; q < 4; q++) c3[0][q] = 0.f;
#pragma unroll
    for (int j = 0; j < 2; j++)
#pragma unroll
        for (int q = 0; q < 4; q++) c4[j][q] = 0.f;

    // ---- phase 2: decoder. accL3 enters each t as zin3 + Whh3@h3(t-1). ----
    ull accL3[1][4][2], accL4[2][4][2];
#pragma unroll
    for (int g = 0; g < 4; g++) {
        accL3[0][g][0] = zin3[0][g][0];
        accL3[0][g][1] = zin3[0][g][1];
    }

    for (int t = 0; t < TT; t++) {
        const int p = t & 1;
        if (grpA) {
            act_store<1>(accL3, c3, sh + H2o + (p ^ 1) * 2176 + uB * RS, pr0);
            init_acc<2>(accL4, b4p);
            accumG<2>(sh + H1o + p * 4352, gW4 + 32 * 512, 512, 64, accL4, pr0);
        } else {
            init_acc<2>(accL4, b4p);
            accumG<2>(sh + H1o + p * 4352, gW4 + 32 * 512, 512, 64, accL4, pr0);
        }
        if (t > 0) {   // projection of h4(t-1) from H1[p], overlapped
            const float* h4 = sh + H1o + p * 4352;
            ull a0 = boutp;
#pragma unroll 8
            for (int j = 0; j < 64; j++) {
                ull w  = *reinterpret_cast<const ull*>(sh + WOd + j * 32 + 2 * fo);
                ull hq = *reinterpret_cast<const ull*>(h4 + j * RS + prb);
                ffma2(a0, w, hq);
            }
            float2 y = unpack2(a0);
            long ob = (row0 + rr) * (TT * 16) + (t - 1) * 16 + fo;
            out[ob]           = y.x;
            out[ob + TT * 16] = y.y;
        }
        if (!grpA)
            act_store<1>(accL3, c3, sh + H2o + (p ^ 1) * 2176 + uB * RS, pr0);
        __syncthreads();
        accumG<2>(sh + H2o + (p ^ 1) * 2176, gW4, 512, 32, accL4, pr0);
        if (grpA) {
            act_store<2>(accL4, c4, sh + H1o + (p ^ 1) * 4352 + uA0 * RS, pr0);
#pragma unroll
            for (int g = 0; g < 4; g++) {
                accL3[0][g][0] = zin3[0][g][0];
                accL3[0][g][1] = zin3[0][g][1];
            }
            accumG<1>(sh + H2o + (p ^ 1) * 2176, gW3, 256, 32, accL3, pr0);
        } else {
#pragma unroll
            for (int g = 0; g < 4; g++) {
                accL3[0][g][0] = zin3[0][g][0];
                accL3[0][g][1] = zin3[0][g][1];
            }
            accumG<1>(sh + H2o + (p ^ 1) * 2176, gW3, 256, 32, accL3, pr0);
            act_store<2>(accL4, c4, sh + H1o + (p ^ 1) * 4352 + uA0 * RS, pr0);
        }
        __syncthreads();
    }
    // final projection: h4(29) in H1 buf 0
    {
        const float* h4 = sh + H1o;
        ull a0 = boutp;
#pragma unroll 8
        for (int j = 0; j < 64; j++) {
            ull w  = *reinterpret_cast<const ull*>(sh + WOd + j * 32 + 2 * fo);
            ull hq = *reinterpret_cast<const ull*>(h4 + j * RS + prb);
            ffma2(a0, w, hq);
        }
        float2 y = unpack2(a0);
        long ob = (row0 + rr) * (TT * 16) + (TT - 1) * 16 + fo;
        out[ob]           = y.x;
        out[ob + TT * 16] = y.y;
    }
}

extern "C" void kernel_launch(void* const* d_in, const int* in_sizes, int n_in,
                              void* d_out, int out_size)
{
    const float* x    = (const float*)d_in[0];
    const float* Wih1 = (const float*)d_in[1];
    const float* Whh1 = (const float*)d_in[2];
    const float* b1   = (const float*)d_in[3];
    const float* Wih2 = (const float*)d_in[4];
    const float* Whh2 = (const float*)d_in[5];
    const float* b2   = (const float*)d_in[6];
    const float* Wih3 = (const float*)d_in[7];
    const float* Whh3 = (const float*)d_in[8];
    const float* b3   = (const float*)d_in[9];
    const float* Wih4 = (const float*)d_in[10];
    const float* Whh4 = (const float*)d_in[11];
    const float* b4   = (const float*)d_in[12];
    const float* Wout = (const float*)d_in[13];
    const float* bout = (const float*)d_in[14];
    float* out = (float*)d_out;

    prep_w<<<512, 256>>>(Wih1, Whh1, Wih2, Whh2, Wih3, Whh3, Wih4, Whh4);

    cudaFuncSetAttribute(lstm_ae, cudaFuncAttributeMaxDynamicSharedMemorySize,
                         SHF * (int)sizeof(float));
    lstm_ae<<<128, THREADS, SHF * sizeof(float)>>>(
        x, b1, b2, b3, b4, Wout, bout, out);
}